// round 13
// baseline (speedup 1.0000x reference)
#include <cuda_runtime.h>
#include <math.h>

#define Bb     64
#define NN     8192
#define WW     64
#define MODES  16
#define NL     4
#define JD     32          // 2*MODES real coefficients
#define KF     96          // 64 channels + 32 basis rows
#define NT     64          // n-tiles of 128
#define TN     128
#define RG     8           // reduction groups (NT/RG tiles each)
#define ATP    64          // At row stride (reads are warp-uniform broadcasts)

typedef unsigned long long ull;

// ---------------- device scratch (static, allocation-free) ----------------
__device__ float g_h0[(size_t)Bb * WW * NN];          // 128 MB
__device__ float g_h1[(size_t)Bb * WW * NN];          // 128 MB
__device__ float g_part[(size_t)Bb * NT * WW * JD];   // per-tile DFT partials (32 MB)
__device__ float g_red[(size_t)Bb * RG * WW * JD];    // stage-1 reduced partials (4 MB)
__device__ float g_mixed[Bb * WW * JD];               // scaled mixed modes
__device__ float g_basis[NN * JD];                    // [n][j]: cos / -sin
__device__ float g_wt[NL * MODES * WW * 2 * WW];      // [(l,m,i)][re(64)|im(64)]

// ---------------- packed f32x2 helpers ------------------------------------
__device__ __forceinline__ ull pk2(float lo, float hi) {
    ull r; asm("mov.b64 %0,{%1,%2};" : "=l"(r) : "f"(lo), "f"(hi)); return r;
}
__device__ __forceinline__ void upk2(ull v, float& lo, float& hi) {
    asm("mov.b64 {%0,%1},%2;" : "=f"(lo), "=f"(hi) : "l"(v));
}
__device__ __forceinline__ ull fma2(ull a, ull b, ull c) {
    ull d; asm("fma.rn.f32x2 %0,%1,%2,%3;" : "=l"(d) : "l"(a), "l"(b), "l"(c)); return d;
}

__device__ __forceinline__ float gelu_exact(float v) {
    return 0.5f * v * (1.0f + erff(v * 0.70710678118654752f));
}

// ---------------- basis table: [n][2m]=cos, [2m+1]=-sin --------------------
__global__ void init_basis_kernel() {
    int idx = blockIdx.x * blockDim.x + threadIdx.x;   // NN*MODES
    if (idx >= NN * MODES) return;
    int m = idx & (MODES - 1);
    int n = idx >> 4;
    int prod = (n * m) & (NN - 1);
    float ang = (float)prod * (6.2831853071795864769f / (float)NN);
    float s, c;
    sincosf(ang, &s, &c);
    g_basis[n * JD + 2 * m]     = c;
    g_basis[n * JD + 2 * m + 1] = -s;
}

// ---------------- transpose spectral weights to [(l,m,i)][re|im] -----------
__global__ void transpose_w_kernel(const float* __restrict__ swr,
                                   const float* __restrict__ swi) {
    int idx = blockIdx.x * blockDim.x + threadIdx.x;   // NL*MODES*W*W
    if (idx >= NL * MODES * WW * WW) return;
    int o = idx & 63;
    int i = (idx >> 6) & 63;
    int m = (idx >> 12) & 15;
    int l = idx >> 16;
    int src = (((l * WW + i) * WW + o) << 4) + m;
    int dst = (((l * MODES + m) * WW + i) << 7);
    g_wt[dst + o]      = swr[src];
    g_wt[dst + 64 + o] = swi[src];
}

// ---------------- shared DFT-partial phase ---------------------------------
__device__ __forceinline__ void dft_phase(const float* __restrict__ Ts,
                                          const float* __restrict__ Ej,
                                          int b, int nt, int tx, int ty) {
    ull acc[8];
#pragma unroll
    for (int u = 0; u < 8; u++) acc[u] = 0ULL;
#pragma unroll 8
    for (int n2 = 0; n2 < 64; n2++) {
        ull e2 = *(const ull*)&Ej[tx * 130 + 2 * n2];
#pragma unroll
        for (int u = 0; u < 8; u++) {
            ull t2 = *(const ull*)&Ts[(ty + 8 * u) * 132 + 2 * n2];
            acc[u] = fma2(t2, e2, acc[u]);
        }
    }
    float* gp = g_part + (size_t)(b * NT + nt) * WW * JD;
#pragma unroll
    for (int u = 0; u < 8; u++) {
        float lo, hi; upk2(acc[u], lo, hi);
        gp[(ty + 8 * u) * JD + tx] = lo + hi;
    }
}

// ---------------- fc0 tile + DFT partial -----------------------------------
__global__ void __launch_bounds__(256) fc0_dft_kernel(
        const float* __restrict__ x, const float* __restrict__ t,
        const float* __restrict__ w, const float* __restrict__ bias) {
    extern __shared__ float sm[];
    float* Ts = sm;                // 64*132
    float* Ej = sm + 64 * 132;     // 32*130
    int nt = blockIdx.x, b = blockIdx.y, n0 = nt * TN;
    int tid = threadIdx.x, tx = tid & 31, ty = tid >> 5;

    for (int idx = tid; idx < 32 * 128; idx += 256) {
        int j = idx & 31, n = idx >> 5;
        Ej[j * 130 + n] = g_basis[(n0 + n) * JD + j];
    }
    float4 x4 = *(const float4*)&x[(size_t)b * NN + n0 + tx * 4];
    float4 t4 = *(const float4*)&t[(size_t)b * NN + n0 + tx * 4];
#pragma unroll
    for (int u = 0; u < 8; u++) {
        int c = ty + 8 * u;
        float w0 = __ldg(w + c), w1 = __ldg(w + WW + c), bb = __ldg(bias + c);
        float4 v;
        v.x = fmaf(x4.x, w0, fmaf(t4.x, w1, bb));
        v.y = fmaf(x4.y, w0, fmaf(t4.y, w1, bb));
        v.z = fmaf(x4.z, w0, fmaf(t4.z, w1, bb));
        v.w = fmaf(x4.w, w0, fmaf(t4.w, w1, bb));
        *(float4*)&g_h0[(size_t)(b * WW + c) * NN + n0 + tx * 4] = v;
        *(float4*)&Ts[c * 132 + tx * 4] = v;
    }
    __syncthreads();
    dft_phase(Ts, Ej, b, nt, tx, ty);
}

// ---------------- stage-1 reduction: 64 tiles -> 8 groups ------------------
__global__ void __launch_bounds__(256) reduce_part_kernel() {
    int g = blockIdx.x, b = blockIdx.y, tid = threadIdx.x;
    const float* gp = g_part + (size_t)(b * NT + g * (NT / RG)) * WW * JD;
    float* gr = g_red + (size_t)(b * RG + g) * WW * JD;
#pragma unroll
    for (int q = 0; q < 8; q++) {
        int idx = tid + 256 * q;
        float a = 0.0f;
#pragma unroll
        for (int nt = 0; nt < NT / RG; nt++) a += gp[(size_t)nt * WW * JD + idx];
        gr[idx] = a;
    }
}

// ---------------- mode mixing: final reduce + complex mix + scale ----------
__global__ void __launch_bounds__(256) mode_mix_kernel(int l) {
    __shared__ float Fs[WW * JD];   // [i][j]
    int b = blockIdx.x, tid = threadIdx.x;
#pragma unroll
    for (int q = 0; q < 8; q++) {
        int idx = tid + 256 * q;
        const float* gr = g_red + (size_t)b * RG * WW * JD + idx;
        float a = 0.0f;
#pragma unroll
        for (int g = 0; g < RG; g++) a += gr[(size_t)g * WW * JD];
        Fs[idx] = a;
    }
    __syncthreads();
#pragma unroll
    for (int q = 0; q < 4; q++) {
        int om = tid + 256 * q;
        int o = om & 63, m = om >> 6;
        float ar = 0.0f, ai = 0.0f;
        const float* wp = g_wt + (size_t)((l * MODES + m) * WW) * 128 + o;
#pragma unroll 4
        for (int i = 0; i < WW; i++) {
            float fr = Fs[i * JD + 2 * m], fi = Fs[i * JD + 2 * m + 1];
            float wr = wp[i * 128], wi = wp[i * 128 + 64];
            ar = fmaf(fr, wr, fmaf(-fi, wi, ar));
            ai = fmaf(fr, wi, fmaf(fi, wr, ai));
        }
        float sc = (m == 0) ? (1.0f / NN) : (2.0f / NN);
        g_mixed[(b * WW + o) * JD + 2 * m]     = ar * sc;
        g_mixed[(b * WW + o) * JD + 2 * m + 1] = ai * sc;
    }
}

// ---------------- shared GEMM phase (o-pair packed operands) ---------------
// At[k][o] transposed A; Bs[k][n] h|basis. Thread: o = ty*8..+7 (4 pairs),
// n = tx*4..+3. acc[p][n] packs outputs (o=ty*8+2p, o+1).
__device__ __forceinline__ void layer_gemm(float* At, float* Bs,
        const float* __restrict__ hin, const float* __restrict__ cw,
        int l, int b, int n0, int tid, int tx, int ty, ull acc[4][4]) {
    for (int idx = tid; idx < 64 * 64; idx += 256) {
        int o = idx >> 6, c = idx & 63;
        At[c * ATP + o] = cw[(l * WW + o) * WW + c];
    }
    for (int idx = tid; idx < 64 * 32; idx += 256) {
        int o = idx >> 5, j = idx & 31;
        At[(64 + j) * ATP + o] = g_mixed[(b * WW + o) * JD + j];
    }
    for (int idx = tid; idx < 64 * 128; idx += 256) {
        int c = idx >> 7, n = idx & 127;
        Bs[c * 132 + n] = hin[(size_t)(b * WW + c) * NN + n0 + n];
    }
    for (int idx = tid; idx < 32 * 128; idx += 256) {
        int j = idx & 31, n = idx >> 5;
        Bs[(64 + j) * 132 + n] = g_basis[(n0 + n) * JD + j];
    }
    __syncthreads();

#pragma unroll
    for (int p = 0; p < 4; p++)
#pragma unroll
        for (int n = 0; n < 4; n++) acc[p][n] = 0ULL;

#pragma unroll 4
    for (int k = 0; k < KF; k++) {
        float4 aL = *(const float4*)&At[k * ATP + ty * 8];
        float4 aH = *(const float4*)&At[k * ATP + ty * 8 + 4];
        float4 bq = *(const float4*)&Bs[k * 132 + tx * 4];
        ull ap[4];
        ap[0] = pk2(aL.x, aL.y); ap[1] = pk2(aL.z, aL.w);
        ap[2] = pk2(aH.x, aH.y); ap[3] = pk2(aH.z, aH.w);
        ull bb[4];
        bb[0] = pk2(bq.x, bq.x); bb[1] = pk2(bq.y, bq.y);
        bb[2] = pk2(bq.z, bq.z); bb[3] = pk2(bq.w, bq.w);
#pragma unroll
        for (int p = 0; p < 4; p++)
#pragma unroll
            for (int n = 0; n < 4; n++)
                acc[p][n] = fma2(ap[p], bb[n], acc[p][n]);
    }
    __syncthreads();   // done reading At/Bs; safe to repurpose
}

// ---------------- fused layer 0..2: irfft + conv + bias + GELU + DFT -------
__global__ void __launch_bounds__(256, 3) fused_layer_kernel(int src,
        const float* __restrict__ cw, const float* __restrict__ cb, int l) {
    extern __shared__ float sm[];
    float* At = sm;                 // [96][ATP]  (reused as Ej 32*130)
    float* Bs = sm + KF * ATP;      // [96][132]  (rows 0..63 reused as Ts)
    const float* __restrict__ hin = src ? g_h1 : g_h0;
    float* __restrict__ hout      = src ? g_h0 : g_h1;
    int nt = blockIdx.x, b = blockIdx.y, n0 = nt * TN;
    int tid = threadIdx.x, tx = tid & 31, ty = tid >> 5;

    ull acc[4][4];
    layer_gemm(At, Bs, hin, cw, l, b, n0, tid, tx, ty, acc);

    float* Ts = Bs;    // [64][132]
    float* Ej = At;    // [32][130]
    for (int idx = tid; idx < 32 * 128; idx += 256) {
        int j = idx & 31, n = idx >> 5;
        Ej[j * 130 + n] = g_basis[(n0 + n) * JD + j];
    }
#pragma unroll
    for (int p = 0; p < 4; p++) {
        int o0 = ty * 8 + 2 * p, o1 = o0 + 1;
        float bi0 = __ldg(cb + l * WW + o0);
        float bi1 = __ldg(cb + l * WW + o1);
        float4 v0, v1;
        upk2(acc[p][0], v0.x, v1.x);
        upk2(acc[p][1], v0.y, v1.y);
        upk2(acc[p][2], v0.z, v1.z);
        upk2(acc[p][3], v0.w, v1.w);
        v0.x = gelu_exact(v0.x + bi0); v0.y = gelu_exact(v0.y + bi0);
        v0.z = gelu_exact(v0.z + bi0); v0.w = gelu_exact(v0.w + bi0);
        v1.x = gelu_exact(v1.x + bi1); v1.y = gelu_exact(v1.y + bi1);
        v1.z = gelu_exact(v1.z + bi1); v1.w = gelu_exact(v1.w + bi1);
        *(float4*)&hout[(size_t)(b * WW + o0) * NN + n0 + tx * 4] = v0;
        *(float4*)&hout[(size_t)(b * WW + o1) * NN + n0 + tx * 4] = v1;
        *(float4*)&Ts[o0 * 132 + tx * 4] = v0;
        *(float4*)&Ts[o1 * 132 + tx * 4] = v1;
    }
    __syncthreads();
    dft_phase(Ts, Ej, b, nt, tx, ty);
}

// ---------------- fused LAST layer: conv tile + fc1 + GELU + fc2 -----------
__global__ void __launch_bounds__(256, 2) fused_last_kernel(int src,
        const float* __restrict__ cw, const float* __restrict__ cb,
        const float* __restrict__ fc1w, const float* __restrict__ fc1b,
        const float* __restrict__ fc2w, const float* __restrict__ fc2b,
        float* __restrict__ out) {
    extern __shared__ float sm[];
    float* At  = sm;                        // [96][ATP]
    float* Bs  = sm + KF * ATP;             // [96][132]
    float* W1s = sm + KF * ATP + KF * 132;  // [64][128]
    __shared__ float ps2[8 * 128];
    const float* __restrict__ hin = src ? g_h1 : g_h0;
    int nt = blockIdx.x, b = blockIdx.y, n0 = nt * TN;
    int tid = threadIdx.x, tx = tid & 31, ty = tid >> 5;

    // W1s[k][j] straight layout (j-pairs naturally contiguous; reads broadcast)
    for (int idx = tid; idx < 64 * 128; idx += 256) {
        int k = idx >> 7, j = idx & 127;
        W1s[k * 128 + j] = fc1w[idx];
    }

    ull acc[4][4];
    layer_gemm(At, Bs, hin, cw, NL - 1, b, n0, tid, tx, ty, acc);

    float* Ts = Bs;    // [64][132]
#pragma unroll
    for (int p = 0; p < 4; p++) {
        int o0 = ty * 8 + 2 * p, o1 = o0 + 1;
        float bi0 = __ldg(cb + (NL - 1) * WW + o0);
        float bi1 = __ldg(cb + (NL - 1) * WW + o1);
        float4 v0, v1;
        upk2(acc[p][0], v0.x, v1.x);
        upk2(acc[p][1], v0.y, v1.y);
        upk2(acc[p][2], v0.z, v1.z);
        upk2(acc[p][3], v0.w, v1.w);
        v0.x += bi0; v0.y += bi0; v0.z += bi0; v0.w += bi0;   // no gelu last layer
        v1.x += bi1; v1.y += bi1; v1.z += bi1; v1.w += bi1;
        *(float4*)&Ts[o0 * 132 + tx * 4] = v0;
        *(float4*)&Ts[o1 * 132 + tx * 4] = v1;
    }
    __syncthreads();

    // fc1 GEMM: thread j = ty*16..+15 (8 pairs), n = tx*4..+3
    ull acc2[8][4];
#pragma unroll
    for (int p = 0; p < 8; p++)
#pragma unroll
        for (int n = 0; n < 4; n++) acc2[p][n] = 0ULL;

#pragma unroll 4
    for (int k = 0; k < 64; k++) {
        float4 bq = *(const float4*)&Ts[k * 132 + tx * 4];
        ull bb[4];
        bb[0] = pk2(bq.x, bq.x); bb[1] = pk2(bq.y, bq.y);
        bb[2] = pk2(bq.z, bq.z); bb[3] = pk2(bq.w, bq.w);
        float4 w0 = *(const float4*)&W1s[k * 128 + ty * 16];
        float4 w1 = *(const float4*)&W1s[k * 128 + ty * 16 + 4];
        float4 w2 = *(const float4*)&W1s[k * 128 + ty * 16 + 8];
        float4 w3 = *(const float4*)&W1s[k * 128 + ty * 16 + 12];
        ull wp[8];
        wp[0] = pk2(w0.x, w0.y); wp[1] = pk2(w0.z, w0.w);
        wp[2] = pk2(w1.x, w1.y); wp[3] = pk2(w1.z, w1.w);
        wp[4] = pk2(w2.x, w2.y); wp[5] = pk2(w2.z, w2.w);
        wp[6] = pk2(w3.x, w3.y); wp[7] = pk2(w3.z, w3.w);
#pragma unroll
        for (int p = 0; p < 8; p++)
#pragma unroll
            for (int n = 0; n < 4; n++)
                acc2[p][n] = fma2(wp[p], bb[n], acc2[p][n]);
    }

    float sacc[4] = {0.0f, 0.0f, 0.0f, 0.0f};
#pragma unroll
    for (int p = 0; p < 8; p++) {
        int j0 = ty * 16 + 2 * p, j1 = j0 + 1;
        float bj0 = __ldg(fc1b + j0), bj1 = __ldg(fc1b + j1);
        float wz0 = __ldg(fc2w + j0), wz1 = __ldg(fc2w + j1);
#pragma unroll
        for (int n = 0; n < 4; n++) {
            float g0, g1;
            upk2(acc2[p][n], g0, g1);
            sacc[n] = fmaf(wz0, gelu_exact(g0 + bj0), sacc[n]);
            sacc[n] = fmaf(wz1, gelu_exact(g1 + bj1), sacc[n]);
        }
    }
#pragma unroll
    for (int i = 0; i < 4; i++) ps2[ty * 128 + tx * 4 + i] = sacc[i];
    __syncthreads();

    if (tid < 128) {
        float s = __ldg(fc2b);
#pragma unroll
        for (int g = 0; g < 8; g++) s += ps2[g * 128 + tid];
        out[(size_t)b * NN + n0 + tid] = s;
    }
}

// ---------------- launch orchestration ------------------------------------
extern "C" void kernel_launch(void* const* d_in, const int* in_sizes, int n_in,
                              void* d_out, int out_size) {
    const float* x     = (const float*)d_in[0];
    const float* t     = (const float*)d_in[1];
    const float* fc0_w = (const float*)d_in[2];
    const float* fc0_b = (const float*)d_in[3];
    const float* sw_r  = (const float*)d_in[4];
    const float* sw_i  = (const float*)d_in[5];
    const float* cw    = (const float*)d_in[6];
    const float* cb    = (const float*)d_in[7];
    const float* fc1_w = (const float*)d_in[8];
    const float* fc1_b = (const float*)d_in[9];
    const float* fc2_w = (const float*)d_in[10];
    const float* fc2_b = (const float*)d_in[11];
    float* out = (float*)d_out;

    const int smem_fc0   = (64 * 132 + 32 * 130) * 4;              // 50432
    const int smem_fused = (KF * ATP + KF * 132) * 4;              // 75264
    const int smem_last  = (KF * ATP + KF * 132 + 64 * 128) * 4;   // 108032

    cudaFuncSetAttribute(fc0_dft_kernel,
                         cudaFuncAttributeMaxDynamicSharedMemorySize, smem_fc0);
    cudaFuncSetAttribute(fused_layer_kernel,
                         cudaFuncAttributeMaxDynamicSharedMemorySize, smem_fused);
    cudaFuncSetAttribute(fused_last_kernel,
                         cudaFuncAttributeMaxDynamicSharedMemorySize, smem_last);

    init_basis_kernel<<<512, 256>>>();
    transpose_w_kernel<<<1024, 256>>>(sw_r, sw_i);
    fc0_dft_kernel<<<dim3(NT, Bb), 256, smem_fc0>>>(x, t, fc0_w, fc0_b);

    int src = 0;  // current h buffer: 0 -> g_h0
    for (int l = 0; l < NL - 1; l++) {
        reduce_part_kernel<<<dim3(RG, Bb), 256>>>();
        mode_mix_kernel<<<Bb, 256>>>(l);
        fused_layer_kernel<<<dim3(NT, Bb), 256, smem_fused>>>(src, cw, cb, l);
        src ^= 1;
    }
    reduce_part_kernel<<<dim3(RG, Bb), 256>>>();
    mode_mix_kernel<<<Bb, 256>>>(NL - 1);
    fused_last_kernel<<<dim3(NT, Bb), 256, smem_last>>>(
        src, cw, cb, fc1_w, fc1_b, fc2_w, fc2_b, out);
}

// round 17
// speedup vs baseline: 1.5615x; 1.5615x over previous
#include <cuda_runtime.h>
#include <math.h>

#define Bb     64
#define NN     8192
#define WW     64
#define MODES  16
#define NL     4
#define JD     32          // 2*MODES real coefficients
#define KF     96          // 64 channels + 32 basis rows
#define NT     64          // n-tiles of 128
#define TN     128
#define RG     8           // reduction groups (NT/RG tiles each)
#define ATP    64          // At row stride (reads are warp-uniform broadcasts)

typedef unsigned long long ull;

// ---------------- device scratch (static, allocation-free) ----------------
__device__ float g_h0[(size_t)Bb * WW * NN];          // 128 MB
__device__ float g_h1[(size_t)Bb * WW * NN];          // 128 MB
__device__ float g_part[(size_t)Bb * NT * WW * JD];   // per-tile DFT partials (32 MB)
__device__ float g_red[(size_t)Bb * RG * WW * JD];    // stage-1 reduced partials (4 MB)
__device__ float g_mixed[Bb * WW * JD];               // scaled mixed modes
__device__ float g_basis[NN * JD];                    // [n][j]: cos / -sin
__device__ float g_wt[NL * MODES * WW * 2 * WW];      // [(l,m,i)][re(64)|im(64)]

// ---------------- packed f32x2 helpers ------------------------------------
__device__ __forceinline__ ull pk2(float lo, float hi) {
    ull r; asm("mov.b64 %0,{%1,%2};" : "=l"(r) : "f"(lo), "f"(hi)); return r;
}
__device__ __forceinline__ void upk2(ull v, float& lo, float& hi) {
    asm("mov.b64 {%0,%1},%2;" : "=f"(lo), "=f"(hi) : "l"(v));
}
__device__ __forceinline__ ull fma2(ull a, ull b, ull c) {
    ull d; asm("fma.rn.f32x2 %0,%1,%2,%3;" : "=l"(d) : "l"(a), "l"(b), "l"(c)); return d;
}

__device__ __forceinline__ float gelu_exact(float v) {
    return 0.5f * v * (1.0f + erff(v * 0.70710678118654752f));
}

// ---------------- basis table: [n][2m]=cos, [2m+1]=-sin --------------------
__global__ void init_basis_kernel() {
    int idx = blockIdx.x * blockDim.x + threadIdx.x;   // NN*MODES
    if (idx >= NN * MODES) return;
    int m = idx & (MODES - 1);
    int n = idx >> 4;
    int prod = (n * m) & (NN - 1);
    float ang = (float)prod * (6.2831853071795864769f / (float)NN);
    float s, c;
    sincosf(ang, &s, &c);
    g_basis[n * JD + 2 * m]     = c;
    g_basis[n * JD + 2 * m + 1] = -s;
}

// ---------------- transpose spectral weights to [(l,m,i)][re|im] -----------
__global__ void transpose_w_kernel(const float* __restrict__ swr,
                                   const float* __restrict__ swi) {
    int idx = blockIdx.x * blockDim.x + threadIdx.x;   // NL*MODES*W*W
    if (idx >= NL * MODES * WW * WW) return;
    int o = idx & 63;
    int i = (idx >> 6) & 63;
    int m = (idx >> 12) & 15;
    int l = idx >> 16;
    int src = (((l * WW + i) * WW + o) << 4) + m;
    int dst = (((l * MODES + m) * WW + i) << 7);
    g_wt[dst + o]      = swr[src];
    g_wt[dst + 64 + o] = swi[src];
}

// ---------------- shared DFT-partial phase ---------------------------------
__device__ __forceinline__ void dft_phase(const float* __restrict__ Ts,
                                          const float* __restrict__ Ej,
                                          int b, int nt, int tx, int ty) {
    ull acc[8];
#pragma unroll
    for (int u = 0; u < 8; u++) acc[u] = 0ULL;
#pragma unroll 8
    for (int n2 = 0; n2 < 64; n2++) {
        ull e2 = *(const ull*)&Ej[tx * 130 + 2 * n2];
#pragma unroll
        for (int u = 0; u < 8; u++) {
            ull t2 = *(const ull*)&Ts[(ty + 8 * u) * 132 + 2 * n2];
            acc[u] = fma2(t2, e2, acc[u]);
        }
    }
    float* gp = g_part + (size_t)(b * NT + nt) * WW * JD;
#pragma unroll
    for (int u = 0; u < 8; u++) {
        float lo, hi; upk2(acc[u], lo, hi);
        gp[(ty + 8 * u) * JD + tx] = lo + hi;
    }
}

// ---------------- fc0 tile + DFT partial -----------------------------------
__global__ void __launch_bounds__(256) fc0_dft_kernel(
        const float* __restrict__ x, const float* __restrict__ t,
        const float* __restrict__ w, const float* __restrict__ bias) {
    extern __shared__ float sm[];
    float* Ts = sm;                // 64*132
    float* Ej = sm + 64 * 132;     // 32*130
    int nt = blockIdx.x, b = blockIdx.y, n0 = nt * TN;
    int tid = threadIdx.x, tx = tid & 31, ty = tid >> 5;

    for (int idx = tid; idx < 32 * 128; idx += 256) {
        int j = idx & 31, n = idx >> 5;
        Ej[j * 130 + n] = g_basis[(n0 + n) * JD + j];
    }
    float4 x4 = *(const float4*)&x[(size_t)b * NN + n0 + tx * 4];
    float4 t4 = *(const float4*)&t[(size_t)b * NN + n0 + tx * 4];
#pragma unroll
    for (int u = 0; u < 8; u++) {
        int c = ty + 8 * u;
        float w0 = __ldg(w + c), w1 = __ldg(w + WW + c), bb = __ldg(bias + c);
        float4 v;
        v.x = fmaf(x4.x, w0, fmaf(t4.x, w1, bb));
        v.y = fmaf(x4.y, w0, fmaf(t4.y, w1, bb));
        v.z = fmaf(x4.z, w0, fmaf(t4.z, w1, bb));
        v.w = fmaf(x4.w, w0, fmaf(t4.w, w1, bb));
        *(float4*)&g_h0[(size_t)(b * WW + c) * NN + n0 + tx * 4] = v;
        *(float4*)&Ts[c * 132 + tx * 4] = v;
    }
    __syncthreads();
    dft_phase(Ts, Ej, b, nt, tx, ty);
}

// ---------------- stage-1 reduction: 64 tiles -> 8 groups ------------------
__global__ void __launch_bounds__(256) reduce_part_kernel() {
    int g = blockIdx.x, b = blockIdx.y, tid = threadIdx.x;
    const float* gp = g_part + (size_t)(b * NT + g * (NT / RG)) * WW * JD;
    float* gr = g_red + (size_t)(b * RG + g) * WW * JD;
#pragma unroll
    for (int q = 0; q < 8; q++) {
        int idx = tid + 256 * q;
        float a = 0.0f;
#pragma unroll
        for (int nt = 0; nt < NT / RG; nt++) a += gp[(size_t)nt * WW * JD + idx];
        gr[idx] = a;
    }
}

// ---------------- mode mixing: final reduce + complex mix + scale ----------
__global__ void __launch_bounds__(256) mode_mix_kernel(int l) {
    __shared__ float Fs[WW * JD];   // [i][j]
    int b = blockIdx.x, tid = threadIdx.x;
#pragma unroll
    for (int q = 0; q < 8; q++) {
        int idx = tid + 256 * q;
        const float* gr = g_red + (size_t)b * RG * WW * JD + idx;
        float a = 0.0f;
#pragma unroll
        for (int g = 0; g < RG; g++) a += gr[(size_t)g * WW * JD];
        Fs[idx] = a;
    }
    __syncthreads();
#pragma unroll
    for (int q = 0; q < 4; q++) {
        int om = tid + 256 * q;
        int o = om & 63, m = om >> 6;
        float ar = 0.0f, ai = 0.0f;
        const float* wp = g_wt + (size_t)((l * MODES + m) * WW) * 128 + o;
#pragma unroll 4
        for (int i = 0; i < WW; i++) {
            float fr = Fs[i * JD + 2 * m], fi = Fs[i * JD + 2 * m + 1];
            float wr = wp[i * 128], wi = wp[i * 128 + 64];
            ar = fmaf(fr, wr, fmaf(-fi, wi, ar));
            ai = fmaf(fr, wi, fmaf(fi, wr, ai));
        }
        float sc = (m == 0) ? (1.0f / NN) : (2.0f / NN);
        g_mixed[(b * WW + o) * JD + 2 * m]     = ar * sc;
        g_mixed[(b * WW + o) * JD + 2 * m + 1] = ai * sc;
    }
}

// ---------------- shared GEMM phase (o-pair packed operands) ---------------
// At[k][o] transposed A; Bs[k][n] h|basis. Thread: o = ty*8..+7 (4 pairs),
// n = tx*4..+3. acc[p][n] packs outputs (o=ty*8+2p, o+1).
__device__ __forceinline__ void layer_gemm(float* At, float* Bs,
        const float* __restrict__ hin, const float* __restrict__ cw,
        int l, int b, int n0, int tid, int tx, int ty, ull acc[4][4]) {
    for (int idx = tid; idx < 64 * 64; idx += 256) {
        int o = idx >> 6, c = idx & 63;
        At[c * ATP + o] = cw[(l * WW + o) * WW + c];
    }
    for (int idx = tid; idx < 64 * 32; idx += 256) {
        int o = idx >> 5, j = idx & 31;
        At[(64 + j) * ATP + o] = g_mixed[(b * WW + o) * JD + j];
    }
    for (int idx = tid; idx < 64 * 128; idx += 256) {
        int c = idx >> 7, n = idx & 127;
        Bs[c * 132 + n] = hin[(size_t)(b * WW + c) * NN + n0 + n];
    }
    for (int idx = tid; idx < 32 * 128; idx += 256) {
        int j = idx & 31, n = idx >> 5;
        Bs[(64 + j) * 132 + n] = g_basis[(n0 + n) * JD + j];
    }
    __syncthreads();

#pragma unroll
    for (int p = 0; p < 4; p++)
#pragma unroll
        for (int n = 0; n < 4; n++) acc[p][n] = 0ULL;

#pragma unroll 4
    for (int k = 0; k < KF; k++) {
        float4 aL = *(const float4*)&At[k * ATP + ty * 8];
        float4 aH = *(const float4*)&At[k * ATP + ty * 8 + 4];
        float4 bq = *(const float4*)&Bs[k * 132 + tx * 4];
        ull ap[4];
        ap[0] = pk2(aL.x, aL.y); ap[1] = pk2(aL.z, aL.w);
        ap[2] = pk2(aH.x, aH.y); ap[3] = pk2(aH.z, aH.w);
        ull bb[4];
        bb[0] = pk2(bq.x, bq.x); bb[1] = pk2(bq.y, bq.y);
        bb[2] = pk2(bq.z, bq.z); bb[3] = pk2(bq.w, bq.w);
#pragma unroll
        for (int p = 0; p < 4; p++)
#pragma unroll
            for (int n = 0; n < 4; n++)
                acc[p][n] = fma2(ap[p], bb[n], acc[p][n]);
    }
    __syncthreads();   // done reading At/Bs; safe to repurpose
}

// ---------------- fused layer 0..2: irfft + conv + bias + GELU + DFT -------
__global__ void __launch_bounds__(256) fused_layer_kernel(int src,
        const float* __restrict__ cw, const float* __restrict__ cb, int l) {
    extern __shared__ float sm[];
    float* At = sm;                 // [96][ATP]  (reused as Ej 32*130)
    float* Bs = sm + KF * ATP;      // [96][132]  (rows 0..63 reused as Ts)
    const float* __restrict__ hin = src ? g_h1 : g_h0;
    float* __restrict__ hout      = src ? g_h0 : g_h1;
    int nt = blockIdx.x, b = blockIdx.y, n0 = nt * TN;
    int tid = threadIdx.x, tx = tid & 31, ty = tid >> 5;

    ull acc[4][4];
    layer_gemm(At, Bs, hin, cw, l, b, n0, tid, tx, ty, acc);

    float* Ts = Bs;    // [64][132]
    float* Ej = At;    // [32][130]
    for (int idx = tid; idx < 32 * 128; idx += 256) {
        int j = idx & 31, n = idx >> 5;
        Ej[j * 130 + n] = g_basis[(n0 + n) * JD + j];
    }
#pragma unroll
    for (int p = 0; p < 4; p++) {
        int o0 = ty * 8 + 2 * p, o1 = o0 + 1;
        float bi0 = __ldg(cb + l * WW + o0);
        float bi1 = __ldg(cb + l * WW + o1);
        float4 v0, v1;
        upk2(acc[p][0], v0.x, v1.x);
        upk2(acc[p][1], v0.y, v1.y);
        upk2(acc[p][2], v0.z, v1.z);
        upk2(acc[p][3], v0.w, v1.w);
        v0.x = gelu_exact(v0.x + bi0); v0.y = gelu_exact(v0.y + bi0);
        v0.z = gelu_exact(v0.z + bi0); v0.w = gelu_exact(v0.w + bi0);
        v1.x = gelu_exact(v1.x + bi1); v1.y = gelu_exact(v1.y + bi1);
        v1.z = gelu_exact(v1.z + bi1); v1.w = gelu_exact(v1.w + bi1);
        *(float4*)&hout[(size_t)(b * WW + o0) * NN + n0 + tx * 4] = v0;
        *(float4*)&hout[(size_t)(b * WW + o1) * NN + n0 + tx * 4] = v1;
        *(float4*)&Ts[o0 * 132 + tx * 4] = v0;
        *(float4*)&Ts[o1 * 132 + tx * 4] = v1;
    }
    __syncthreads();
    dft_phase(Ts, Ej, b, nt, tx, ty);
}

// ---------------- fused LAST layer: conv tile + fc1 + GELU + fc2 -----------
__global__ void __launch_bounds__(256) fused_last_kernel(int src,
        const float* __restrict__ cw, const float* __restrict__ cb,
        const float* __restrict__ fc1w, const float* __restrict__ fc1b,
        const float* __restrict__ fc2w, const float* __restrict__ fc2b,
        float* __restrict__ out) {
    extern __shared__ float sm[];
    float* At  = sm;                        // [96][ATP]
    float* Bs  = sm + KF * ATP;             // [96][132]
    float* W1s = sm + KF * ATP + KF * 132;  // [64][128]
    __shared__ float ps2[8 * 128];
    const float* __restrict__ hin = src ? g_h1 : g_h0;
    int nt = blockIdx.x, b = blockIdx.y, n0 = nt * TN;
    int tid = threadIdx.x, tx = tid & 31, ty = tid >> 5;

    // W1s[k][j] straight layout (j-pairs naturally contiguous; reads broadcast)
    for (int idx = tid; idx < 64 * 128; idx += 256) {
        int k = idx >> 7, j = idx & 127;
        W1s[k * 128 + j] = fc1w[idx];
    }

    ull acc[4][4];
    layer_gemm(At, Bs, hin, cw, NL - 1, b, n0, tid, tx, ty, acc);

    float* Ts = Bs;    // [64][132]
#pragma unroll
    for (int p = 0; p < 4; p++) {
        int o0 = ty * 8 + 2 * p, o1 = o0 + 1;
        float bi0 = __ldg(cb + (NL - 1) * WW + o0);
        float bi1 = __ldg(cb + (NL - 1) * WW + o1);
        float4 v0, v1;
        upk2(acc[p][0], v0.x, v1.x);
        upk2(acc[p][1], v0.y, v1.y);
        upk2(acc[p][2], v0.z, v1.z);
        upk2(acc[p][3], v0.w, v1.w);
        v0.x += bi0; v0.y += bi0; v0.z += bi0; v0.w += bi0;   // no gelu last layer
        v1.x += bi1; v1.y += bi1; v1.z += bi1; v1.w += bi1;
        *(float4*)&Ts[o0 * 132 + tx * 4] = v0;
        *(float4*)&Ts[o1 * 132 + tx * 4] = v1;
    }
    __syncthreads();

    // fc1 GEMM: thread j = ty*16..+15 (8 pairs), n = tx*4..+3
    ull acc2[8][4];
#pragma unroll
    for (int p = 0; p < 8; p++)
#pragma unroll
        for (int n = 0; n < 4; n++) acc2[p][n] = 0ULL;

#pragma unroll 4
    for (int k = 0; k < 64; k++) {
        float4 bq = *(const float4*)&Ts[k * 132 + tx * 4];
        ull bb[4];
        bb[0] = pk2(bq.x, bq.x); bb[1] = pk2(bq.y, bq.y);
        bb[2] = pk2(bq.z, bq.z); bb[3] = pk2(bq.w, bq.w);
        float4 w0 = *(const float4*)&W1s[k * 128 + ty * 16];
        float4 w1 = *(const float4*)&W1s[k * 128 + ty * 16 + 4];
        float4 w2 = *(const float4*)&W1s[k * 128 + ty * 16 + 8];
        float4 w3 = *(const float4*)&W1s[k * 128 + ty * 16 + 12];
        ull wp[8];
        wp[0] = pk2(w0.x, w0.y); wp[1] = pk2(w0.z, w0.w);
        wp[2] = pk2(w1.x, w1.y); wp[3] = pk2(w1.z, w1.w);
        wp[4] = pk2(w2.x, w2.y); wp[5] = pk2(w2.z, w2.w);
        wp[6] = pk2(w3.x, w3.y); wp[7] = pk2(w3.z, w3.w);
#pragma unroll
        for (int p = 0; p < 8; p++)
#pragma unroll
            for (int n = 0; n < 4; n++)
                acc2[p][n] = fma2(wp[p], bb[n], acc2[p][n]);
    }

    float sacc[4] = {0.0f, 0.0f, 0.0f, 0.0f};
#pragma unroll
    for (int p = 0; p < 8; p++) {
        int j0 = ty * 16 + 2 * p, j1 = j0 + 1;
        float bj0 = __ldg(fc1b + j0), bj1 = __ldg(fc1b + j1);
        float wz0 = __ldg(fc2w + j0), wz1 = __ldg(fc2w + j1);
#pragma unroll
        for (int n = 0; n < 4; n++) {
            float g0, g1;
            upk2(acc2[p][n], g0, g1);
            sacc[n] = fmaf(wz0, gelu_exact(g0 + bj0), sacc[n]);
            sacc[n] = fmaf(wz1, gelu_exact(g1 + bj1), sacc[n]);
        }
    }
#pragma unroll
    for (int i = 0; i < 4; i++) ps2[ty * 128 + tx * 4 + i] = sacc[i];
    __syncthreads();

    if (tid < 128) {
        float s = __ldg(fc2b);
#pragma unroll
        for (int g = 0; g < 8; g++) s += ps2[g * 128 + tid];
        out[(size_t)b * NN + n0 + tid] = s;
    }
}

// ---------------- launch orchestration ------------------------------------
extern "C" void kernel_launch(void* const* d_in, const int* in_sizes, int n_in,
                              void* d_out, int out_size) {
    const float* x     = (const float*)d_in[0];
    const float* t     = (const float*)d_in[1];
    const float* fc0_w = (const float*)d_in[2];
    const float* fc0_b = (const float*)d_in[3];
    const float* sw_r  = (const float*)d_in[4];
    const float* sw_i  = (const float*)d_in[5];
    const float* cw    = (const float*)d_in[6];
    const float* cb    = (const float*)d_in[7];
    const float* fc1_w = (const float*)d_in[8];
    const float* fc1_b = (const float*)d_in[9];
    const float* fc2_w = (const float*)d_in[10];
    const float* fc2_b = (const float*)d_in[11];
    float* out = (float*)d_out;

    const int smem_fc0   = (64 * 132 + 32 * 130) * 4;              // 50432
    const int smem_fused = (KF * ATP + KF * 132) * 4;              // 75264
    const int smem_last  = (KF * ATP + KF * 132 + 64 * 128) * 4;   // 108032

    cudaFuncSetAttribute(fc0_dft_kernel,
                         cudaFuncAttributeMaxDynamicSharedMemorySize, smem_fc0);
    cudaFuncSetAttribute(fused_layer_kernel,
                         cudaFuncAttributeMaxDynamicSharedMemorySize, smem_fused);
    cudaFuncSetAttribute(fused_last_kernel,
                         cudaFuncAttributeMaxDynamicSharedMemorySize, smem_last);

    init_basis_kernel<<<512, 256>>>();
    transpose_w_kernel<<<1024, 256>>>(sw_r, sw_i);
    fc0_dft_kernel<<<dim3(NT, Bb), 256, smem_fc0>>>(x, t, fc0_w, fc0_b);

    int src = 0;  // current h buffer: 0 -> g_h0
    for (int l = 0; l < NL - 1; l++) {
        reduce_part_kernel<<<dim3(RG, Bb), 256>>>();
        mode_mix_kernel<<<Bb, 256>>>(l);
        fused_layer_kernel<<<dim3(NT, Bb), 256, smem_fused>>>(src, cw, cb, l);
        src ^= 1;
    }
    reduce_part_kernel<<<dim3(RG, Bb), 256>>>();
    mode_mix_kernel<<<Bb, 256>>>(NL - 1);
    fused_last_kernel<<<dim3(NT, Bb), 256, smem_last>>>(
        src, cw, cb, fc1_w, fc1_b, fc2_w, fc2_b, out);
}